// round 14
// baseline (speedup 1.0000x reference)
#include <cuda_runtime.h>
#include <cuda_bf16.h>
#include <cstdint>
#include <cstddef>

// ---------------- problem shape / output packing ----------------
#define BN_ROWS 16384
#define KCODES  8192
#define DDIM    256

#define ZQ_OFF   0
#define IDX_OFF  4194304
#define LOSS_OFF 4210688
#define DIST_OFF 4210689

// ---------------- GEMM tiling ----------------
#define MT 128              // rows per CTA tile
#define NT 128              // codes per CTA tile
#define KC 32               // K chunk (bf16 elems) = one 64B smem row
#define NKCH (DDIM/KC)      // 8 chunks
#define NHALF (KCODES/64)   // 128 argmax candidate slots per row

// smem: SW64-swizzled 64B rows (conflict-free LDSM, no padding)
#define ROWB 64
#define A_HI_OFF 0
#define A_LO_OFF 8192
#define B_HI_OFF 16384
#define B_LO_OFF 24576
#define STAGE_BYTES 32768
#define NSTAGE 3
#define CN_OFF 98304
#define ZN_OFF 98816
#define MB_OFF 99328        // 3x full + 3x empty mbarriers (8B each)
#define SMEM_DYN 99392

// SW64 swizzle: XOR bits[5:4] with bits[9:8] (8-row x 64B atom)
#define SWZ64(o) ((o) ^ (((o) >> 3) & 0x30))

// ---------------- device scratch (allocation-free rule) ----------------
__device__ __nv_bfloat16 g_zhi[BN_ROWS*DDIM];
__device__ __nv_bfloat16 g_zlo[BN_ROWS*DDIM];
__device__ __nv_bfloat16 g_chi[KCODES*DDIM];
__device__ __nv_bfloat16 g_clo[KCODES*DDIM];
__device__ float g_znorm[BN_ROWS];
__device__ float g_cnorm[KCODES];
__device__ float g_bestv[(size_t)BN_ROWS*NHALF];
__device__ int   g_besti[(size_t)BN_ROWS*NHALF];
__device__ int   g_idx[BN_ROWS];
__device__ float g_partial[BN_ROWS];

// ---------------- PTX helpers (all valid on plain sm_103 target) -------------
__device__ __forceinline__ uint32_t smem_u32(const void* p) {
    uint32_t a;
    asm("{ .reg .u64 t; cvta.to.shared.u64 t, %1; cvt.u32.u64 %0, t; }" : "=r"(a) : "l"(p));
    return a;
}
__device__ __forceinline__ void cp16(uint32_t saddr, const void* g) {
    asm volatile("cp.async.cg.shared.global [%0], [%1], 16;" :: "r"(saddr), "l"(g));
}
__device__ __forceinline__ void ldsm_x4(uint32_t* r, uint32_t addr) {
    asm volatile("ldmatrix.sync.aligned.m8n8.x4.shared.b16 {%0,%1,%2,%3}, [%4];"
                 : "=r"(r[0]), "=r"(r[1]), "=r"(r[2]), "=r"(r[3]) : "r"(addr));
}
__device__ __forceinline__ void mma_bf16(float* d, const uint32_t* a, const uint32_t* b) {
    asm volatile(
        "mma.sync.aligned.m16n8k16.row.col.f32.bf16.bf16.f32 "
        "{%0,%1,%2,%3}, {%4,%5,%6,%7}, {%8,%9}, {%0,%1,%2,%3};"
        : "+f"(d[0]), "+f"(d[1]), "+f"(d[2]), "+f"(d[3])
        : "r"(a[0]), "r"(a[1]), "r"(a[2]), "r"(a[3]), "r"(b[0]), "r"(b[1]));
}
__device__ __forceinline__ void mbar_init(uint32_t a, uint32_t cnt) {
    asm volatile("mbarrier.init.shared::cta.b64 [%0], %1;" :: "r"(a), "r"(cnt) : "memory");
}
__device__ __forceinline__ void mbar_wait(uint32_t a, uint32_t parity) {
    asm volatile(
        "{\n\t.reg .pred P;\n\t"
        "W_%=:\n\t"
        "mbarrier.try_wait.parity.shared::cta.b64 P, [%0], %1;\n\t"
        "@P bra D_%=;\n\t"
        "bra W_%=;\n\t"
        "D_%=:\n\t}"
        :: "r"(a), "r"(parity) : "memory");
}
__device__ __forceinline__ void mbar_arrive(uint32_t a) {
    asm volatile("mbarrier.arrive.shared::cta.b64 _, [%0];" :: "r"(a) : "memory");
}
__device__ __forceinline__ void cp_async_arrive(uint32_t a) {
    asm volatile("cp.async.mbarrier.arrive.noinc.shared::cta.b64 [%0];" :: "r"(a) : "memory");
}

// ---------------------------------------------------------------------------
// nop kernels: keep the GEMM at ncu's profiled launch index (3).
// ---------------------------------------------------------------------------
__global__ void nop_kernel() {}
__global__ void nop_kernel2() {}

// ---------------------------------------------------------------------------
// Kernel A: fused bf16 hi/lo split + squared norms. One warp per row.
// ---------------------------------------------------------------------------
__device__ __forceinline__ uint32_t pack2(__nv_bfloat16 a, __nv_bfloat16 b) {
    return (uint32_t)__bfloat16_as_ushort(a) | ((uint32_t)__bfloat16_as_ushort(b) << 16);
}
__device__ __forceinline__ uint2 split8(float4 v, uint2& lo_out) {
    __nv_bfloat16 h0 = __float2bfloat16(v.x), h1 = __float2bfloat16(v.y);
    __nv_bfloat16 h2 = __float2bfloat16(v.z), h3 = __float2bfloat16(v.w);
    __nv_bfloat16 l0 = __float2bfloat16(v.x - __bfloat162float(h0));
    __nv_bfloat16 l1 = __float2bfloat16(v.y - __bfloat162float(h1));
    __nv_bfloat16 l2 = __float2bfloat16(v.z - __bfloat162float(h2));
    __nv_bfloat16 l3 = __float2bfloat16(v.w - __bfloat162float(h3));
    lo_out = make_uint2(pack2(l0, l1), pack2(l2, l3));
    return make_uint2(pack2(h0, h1), pack2(h2, h3));
}
__global__ void prep_kernel(const float* __restrict__ z, const float* __restrict__ cb) {
    int w    = (blockIdx.x * blockDim.x + threadIdx.x) >> 5;
    int lane = threadIdx.x & 31;
    if (w >= BN_ROWS + KCODES) return;
    const float* src; __nv_bfloat16 *hi_b, *lo_b;
    if (w < BN_ROWS) { src = z  + (size_t)w * DDIM;
                       hi_b = g_zhi + (size_t)w * DDIM; lo_b = g_zlo + (size_t)w * DDIM; }
    else             { int j = w - BN_ROWS; src = cb + (size_t)j * DDIM;
                       hi_b = g_chi + (size_t)j * DDIM; lo_b = g_clo + (size_t)j * DDIM; }
    const float4* p = (const float4*)src;
    float4 u = p[lane];
    float4 v = p[lane + 32];
    uint2 ulo, vlo;
    uint2 uhi = split8(u, ulo);
    uint2 vhi = split8(v, vlo);
    ((uint2*)hi_b)[lane]      = uhi;
    ((uint2*)hi_b)[lane + 32] = vhi;
    ((uint2*)lo_b)[lane]      = ulo;
    ((uint2*)lo_b)[lane + 32] = vlo;
    float s = u.x*u.x + u.y*u.y + u.z*u.z + u.w*u.w
            + v.x*v.x + v.y*v.y + v.z*v.z + v.w*v.w;
    #pragma unroll
    for (int o = 16; o > 0; o >>= 1) s += __shfl_xor_sync(0xffffffffu, s, o);
    if (lane == 0) {
        if (w < BN_ROWS) g_znorm[w] = s;
        else             g_cnorm[w - BN_ROWS] = s;
    }
}

// ---------------------------------------------------------------------------
// Kernel C: HMMA GEMM (3-term bf16 split) + single-pass slab epilogue + argmax.
// R13 mainloop body, but the per-chunk bar.sync/wait_group lockstep is replaced
// by per-stage mbarrier pairs (full: 256 cp.async arrives; empty: 8 warp
// arrives). Warps free-run with ~1-chunk skew so one warp's LDSM bursts hide
// under another's MMA drain.
// ---------------------------------------------------------------------------
__global__ void __launch_bounds__(256, 2) gemm_dist_kernel(float* __restrict__ dist) {
    extern __shared__ char smem[];
    const uint32_t sb = smem_u32(smem);
    const int t    = threadIdx.x;
    const int wid  = t >> 5;
    const int lane = t & 31;
    const int m0 = blockIdx.y * MT;
    const int n0 = blockIdx.x * NT;
    const int wm = (wid >> 1) * 32;   // warp row base within tile
    const int wn = (wid & 1) * 64;    // warp col base within tile

    const uint32_t FULL0  = sb + MB_OFF;        // 3 x 8B
    const uint32_t EMPTY0 = sb + MB_OFF + 24;   // 3 x 8B

    if (t == 0) {
        #pragma unroll
        for (int s = 0; s < NSTAGE; s++) {
            mbar_init(FULL0  + s * 8, 256);
            mbar_init(EMPTY0 + s * 8, 8);
        }
    }
    // stage cn / zn
    if (t < 128)      ((float*)(smem + CN_OFF))[t]       = g_cnorm[n0 + t];
    else              ((float*)(smem + ZN_OFF))[t - 128] = g_znorm[m0 + t - 128];
    __syncthreads();   // mbarrier init + cn/zn visible

    float acc[2][8][4];
    #pragma unroll
    for (int a = 0; a < 2; a++)
        #pragma unroll
        for (int b = 0; b < 8; b++)
            #pragma unroll
            for (int c = 0; c < 4; c++) acc[a][b][c] = 0.f;

    // lane decomposition for LDSM fragments
    const int arow = (lane & 7) + ((lane >> 3) & 1) * 8;   // row within 16
    const int a16  = (lane >> 4) & 1;                      // 16B col select
    const int brow = ((lane >> 4) & 1) * 8 + (lane & 7);
    const int b16  = (lane >> 3) & 1;

    auto load_stage = [&](int chunk, int stg) {
        const uint32_t dstb = sb + stg * STAGE_BYTES;
        const int k0 = chunk * KC;
        #pragma unroll
        for (int q = 0; q < 2; q++) {
            int i   = t + q * 256;        // 0..511
            int row = i >> 2, ch = i & 3;
            uint32_t d = SWZ64((uint32_t)(row * ROWB + ch * 16));
            size_t ga = (size_t)(m0 + row) * DDIM + k0 + ch * 8;
            size_t gb = (size_t)(n0 + row) * DDIM + k0 + ch * 8;
            cp16(dstb + A_HI_OFF + d, g_zhi + ga);
            cp16(dstb + A_LO_OFF + d, g_zlo + ga);
            cp16(dstb + B_HI_OFF + d, g_chi + gb);
            cp16(dstb + B_LO_OFF + d, g_clo + gb);
        }
    };

    // prologue: issue chunks 0 and 1 (stages are virgin, no empty-wait)
    load_stage(0, 0);
    cp_async_arrive(FULL0 + 0 * 8);
    load_stage(1, 1);
    cp_async_arrive(FULL0 + 1 * 8);

    #pragma unroll 1
    for (int c = 0; c < NKCH; c++) {
        const int sidx = c % NSTAGE;
        const uint32_t st = sb + sidx * STAGE_BYTES;

        // ---- producer: issue chunk c+2 into stage (c+2)%3 ----
        if (c + 2 < NKCH) {
            const int c2 = c + 2;
            const int s2 = c2 % NSTAGE;
            if (c2 >= NSTAGE)
                mbar_wait(EMPTY0 + s2 * 8, (uint32_t)((c2 / NSTAGE - 1) & 1));
            load_stage(c2, s2);
            cp_async_arrive(FULL0 + s2 * 8);
        }

        // ---- consumer: wait chunk c's data ----
        mbar_wait(FULL0 + sidx * 8, (uint32_t)((c / NSTAGE) & 1));

        // ---- compute chunk c (R13-proven body) ----
        uint32_t ah[2][2][4], al[2][2][4];
        #pragma unroll
        for (int mt = 0; mt < 2; mt++) {
            uint32_t ad = SWZ64((uint32_t)((wm + mt*16 + arow) * ROWB + a16 * 16));
            ldsm_x4(ah[0][mt], st + A_HI_OFF + ad);
            ldsm_x4(al[0][mt], st + A_LO_OFF + ad);
        }
        #pragma unroll
        for (int s = 0; s < 2; s++) {
            #pragma unroll
            for (int j2 = 0; j2 < 2; j2++) {
                if (s == 0 && j2 == 1) {
                    // prefetch kstep-1 A fragments during kstep-0 MMAs
                    #pragma unroll
                    for (int mt = 0; mt < 2; mt++) {
                        uint32_t ad = SWZ64((uint32_t)((wm + mt*16 + arow) * ROWB
                                                       + 32 + a16 * 16));
                        ldsm_x4(ah[1][mt], st + A_HI_OFF + ad);
                        ldsm_x4(al[1][mt], st + A_LO_OFF + ad);
                    }
                }
                uint32_t bh[2][4], bl[2][4];
                #pragma unroll
                for (int jj = 0; jj < 2; jj++) {
                    uint32_t bd = SWZ64((uint32_t)((wn + (2*j2 + jj)*16 + brow) * ROWB
                                                   + s * 32 + b16 * 16));
                    ldsm_x4(bh[jj], st + B_HI_OFF + bd);
                    ldsm_x4(bl[jj], st + B_LO_OFF + bd);
                }
                // this warp's LAST smem read of stage sidx is the s==1,j2==1 B load:
                // release the stage for the producer of chunk c+3.
                if (s == 1 && j2 == 1 && lane == 0)
                    mbar_arrive(EMPTY0 + sidx * 8);
                #pragma unroll
                for (int jj = 0; jj < 2; jj++)
                    #pragma unroll
                    for (int mt = 0; mt < 2; mt++) {
                        mma_bf16(acc[mt][4*j2 + 2*jj],     ah[s][mt], bh[jj]);
                        mma_bf16(acc[mt][4*j2 + 2*jj + 1], ah[s][mt], bh[jj] + 2);
                    }
                #pragma unroll
                for (int jj = 0; jj < 2; jj++)
                    #pragma unroll
                    for (int mt = 0; mt < 2; mt++) {
                        mma_bf16(acc[mt][4*j2 + 2*jj],     ah[s][mt], bl[jj]);
                        mma_bf16(acc[mt][4*j2 + 2*jj + 1], ah[s][mt], bl[jj] + 2);
                    }
                #pragma unroll
                for (int jj = 0; jj < 2; jj++)
                    #pragma unroll
                    for (int mt = 0; mt < 2; mt++) {
                        mma_bf16(acc[mt][4*j2 + 2*jj],     al[s][mt], bh[jj]);
                        mma_bf16(acc[mt][4*j2 + 2*jj + 1], al[s][mt], bh[jj] + 2);
                    }
            }
        }
    }

    // ---------------- epilogue: single-pass slab + fused argmax ----------------
    const float* cns = (const float*)(smem + CN_OFF);
    const float* zns = (const float*)(smem + ZN_OFF);
    float (*slab)[132] = (float (*)[132])smem;   // 128x132x4B = 67584 <= 98304

    float best[2][2]; int bidx[2][2];
    #pragma unroll
    for (int a = 0; a < 2; a++)
        #pragma unroll
        for (int b = 0; b < 2; b++) { best[a][b] = -3.402823466e38f; bidx[a][b] = 0x7fffffff; }

    __syncthreads();   // all warps done reading stage smem before slab overwrite
    #pragma unroll
    for (int mt = 0; mt < 2; mt++)
        #pragma unroll
        for (int nt = 0; nt < 8; nt++)
            #pragma unroll
            for (int k = 0; k < 4; k++) {
                int rr   = k >> 1;
                int lrow = wm + mt * 16 + (lane >> 2) + rr * 8;
                int col  = wn + nt * 8 + (lane & 3) * 2 + (k & 1);
                float v = fmaf(2.0f, acc[mt][nt][k], -(zns[lrow] + cns[col]));
                slab[lrow][col] = v;
                if (v > best[mt][rr]) { best[mt][rr] = v; bidx[mt][rr] = n0 + col; }
            }
    __syncthreads();
    // coalesced scalar stores (dist base is odd-float offset -> no vectors)
    #pragma unroll
    for (int q = 0; q < 64; q++) {
        int lin = q * 256 + t;        // 0..16383
        int r   = lin >> 7;           // 0..127
        int col = lin & 127;
        dist[(size_t)(m0 + r) * KCODES + n0 + col] = slab[r][col];
    }

    // reduce argmax across the 4 lanes sharing each row
    #pragma unroll
    for (int mt = 0; mt < 2; mt++)
        #pragma unroll
        for (int rr = 0; rr < 2; rr++) {
            float v = best[mt][rr]; int bi = bidx[mt][rr];
            #pragma unroll
            for (int o = 1; o <= 2; o <<= 1) {
                float ov = __shfl_xor_sync(0xffffffffu, v, o);
                int   oi = __shfl_xor_sync(0xffffffffu, bi, o);
                if (ov > v || (ov == v && oi < bi)) { v = ov; bi = oi; }
            }
            if ((lane & 3) == 0) {
                int row = m0 + wm + mt * 16 + (lane >> 2) + rr * 8;
                size_t slot = (size_t)row * NHALF + blockIdx.x * 2 + (wid & 1);
                g_bestv[slot] = v;
                g_besti[slot] = bi;
            }
        }
}

// ---------------------------------------------------------------------------
// Kernel D: final argmax across 128 candidate slots per row (one warp per row)
// ---------------------------------------------------------------------------
__global__ void argmax_final_kernel(float* __restrict__ out_idx) {
    int row  = (blockIdx.x * blockDim.x + threadIdx.x) >> 5;
    int lane = threadIdx.x & 31;
    if (row >= BN_ROWS) return;
    float v = -3.402823466e38f;
    int   bi = 0x7fffffff;
    #pragma unroll
    for (int q = 0; q < 4; q++) {
        size_t s = (size_t)row * NHALF + lane * 4 + q;
        float nv = g_bestv[s];
        int   ni = g_besti[s];
        if (nv > v || (nv == v && ni < bi)) { v = nv; bi = ni; }
    }
    #pragma unroll
    for (int o = 16; o > 0; o >>= 1) {
        float ov = __shfl_xor_sync(0xffffffffu, v, o);
        int   oi = __shfl_xor_sync(0xffffffffu, bi, o);
        if (ov > v || (ov == v && oi < bi)) { v = ov; bi = oi; }
    }
    if (lane == 0) { g_idx[row] = bi; out_idx[row] = (float)bi; }
}

// ---------------------------------------------------------------------------
// Kernel E: zq gather + straight-through + per-row loss partial (float4, 4 rows/CTA)
// ---------------------------------------------------------------------------
__global__ void zq_loss_kernel(const float* __restrict__ z, const float* __restrict__ cb,
                               float* __restrict__ out_zq) {
    const int sub = threadIdx.x >> 6;          // 0..3 row within block
    const int t   = threadIdx.x & 63;          // 64 threads per row (float4)
    const int row = blockIdx.x * 4 + sub;
    const int idx = g_idx[row];
    const float4* zp = (const float4*)(z  + (size_t)row * DDIM);
    const float4* cp = (const float4*)(cb + (size_t)idx * DDIM);
    float4 zv = zp[t], cv = cp[t];
    float4 d  = make_float4(cv.x - zv.x, cv.y - zv.y, cv.z - zv.z, cv.w - zv.w);
    ((float4*)(out_zq + (size_t)row * DDIM))[t] =
        make_float4(zv.x + d.x, zv.y + d.y, zv.z + d.z, zv.w + d.w);
    float s = d.x*d.x + d.y*d.y + d.z*d.z + d.w*d.w;
    #pragma unroll
    for (int o = 16; o > 0; o >>= 1) s += __shfl_xor_sync(0xffffffffu, s, o);
    __shared__ float sm[4][2];
    if ((t & 31) == 0) sm[sub][t >> 5] = s;
    __syncthreads();
    if (t == 0) g_partial[row] = sm[sub][0] + sm[sub][1];
}

// ---------------------------------------------------------------------------
// Kernel F: deterministic final loss reduction
// ---------------------------------------------------------------------------
__global__ void finalize_kernel(float* __restrict__ out_loss) {
    int t = threadIdx.x;
    float s = 0.0f;
    for (int i = t; i < BN_ROWS; i += 256) s += g_partial[i];
    __shared__ float sm[256];
    sm[t] = s;
    __syncthreads();
    for (int o = 128; o > 0; o >>= 1) { if (t < o) sm[t] += sm[t + o]; __syncthreads(); }
    if (t == 0) out_loss[0] = sm[0] / (float)(BN_ROWS * DDIM);
}

// ---------------------------------------------------------------------------
extern "C" void kernel_launch(void* const* d_in, const int* in_sizes, int n_in,
                              void* d_out, int out_size) {
    const float* z  = (const float*)d_in[0];
    const float* cb = (const float*)d_in[1];
    float* out      = (float*)d_out;
    float* out_zq   = out + ZQ_OFF;
    float* out_idx  = out + IDX_OFF;
    float* out_loss = out + LOSS_OFF;
    float* out_dist = out + DIST_OFF;

    cudaFuncSetAttribute(gemm_dist_kernel,
                         cudaFuncAttributeMaxDynamicSharedMemorySize, SMEM_DYN);

    prep_kernel<<<(BN_ROWS + KCODES) / 8, 256>>>(z, cb);        // launch 0 (split+norms)
    nop_kernel<<<1, 32>>>();                                     // launch 1 (slot shim)
    nop_kernel2<<<1, 32>>>();                                    // launch 2 (slot shim)
    gemm_dist_kernel<<<dim3(KCODES / NT, BN_ROWS / MT), 256, SMEM_DYN>>>(out_dist); // launch 3
    argmax_final_kernel<<<(BN_ROWS * 32 + 255) / 256, 256>>>(out_idx);
    zq_loss_kernel<<<BN_ROWS / 4, 256>>>(z, cb, out_zq);
    finalize_kernel<<<1, 256>>>(out_loss);
}

// round 15
// speedup vs baseline: 1.0345x; 1.0345x over previous
#include <cuda_runtime.h>
#include <cuda_bf16.h>
#include <cstdint>
#include <cstddef>

// ---------------- problem shape / output packing ----------------
#define BN_ROWS 16384
#define KCODES  8192
#define DDIM    256

#define ZQ_OFF   0
#define IDX_OFF  4194304
#define LOSS_OFF 4210688
#define DIST_OFF 4210689

// ---------------- GEMM tiling ----------------
#define MT 128              // rows per CTA tile
#define NT 128              // codes per CTA tile
#define KC 32               // K chunk (bf16 elems) = one 64B smem row
#define NKCH (DDIM/KC)      // 8 chunks
#define NHALF (KCODES/64)   // 128 argmax candidate slots per row

// smem: SW64-swizzled 64B rows (conflict-free LDSM, no padding)
#define ROWB 64
#define A_HI_OFF 0
#define A_LO_OFF 8192
#define B_HI_OFF 16384
#define B_LO_OFF 24576
#define STAGE_BYTES 32768
#define NSTAGE 3
#define CN_OFF 98304
#define ZN_OFF 98816
#define SMEM_DYN 99328

// SW64 swizzle: XOR bits[5:4] with bits[9:8] (8-row x 64B atom)
#define SWZ64(o) ((o) ^ (((o) >> 3) & 0x30))

// ---------------- device scratch (allocation-free rule) ----------------
__device__ __nv_bfloat16 g_zhi[BN_ROWS*DDIM];
__device__ __nv_bfloat16 g_zlo[BN_ROWS*DDIM];
__device__ __nv_bfloat16 g_chi[KCODES*DDIM];
__device__ __nv_bfloat16 g_clo[KCODES*DDIM];
__device__ float g_znorm[BN_ROWS];
__device__ float g_cnorm[KCODES];
__device__ float g_bestv[(size_t)BN_ROWS*NHALF];
__device__ int   g_besti[(size_t)BN_ROWS*NHALF];
__device__ float g_partial[BN_ROWS];

// ---------------- PTX helpers (all valid on plain sm_103 target) -------------
__device__ __forceinline__ uint32_t smem_u32(const void* p) {
    uint32_t a;
    asm("{ .reg .u64 t; cvta.to.shared.u64 t, %1; cvt.u32.u64 %0, t; }" : "=r"(a) : "l"(p));
    return a;
}
__device__ __forceinline__ void cp16(uint32_t saddr, const void* g) {
    asm volatile("cp.async.cg.shared.global [%0], [%1], 16;" :: "r"(saddr), "l"(g));
}
__device__ __forceinline__ void ldsm_x4(uint32_t* r, uint32_t addr) {
    asm volatile("ldmatrix.sync.aligned.m8n8.x4.shared.b16 {%0,%1,%2,%3}, [%4];"
                 : "=r"(r[0]), "=r"(r[1]), "=r"(r[2]), "=r"(r[3]) : "r"(addr));
}
__device__ __forceinline__ void mma_bf16(float* d, const uint32_t* a, const uint32_t* b) {
    asm volatile(
        "mma.sync.aligned.m16n8k16.row.col.f32.bf16.bf16.f32 "
        "{%0,%1,%2,%3}, {%4,%5,%6,%7}, {%8,%9}, {%0,%1,%2,%3};"
        : "+f"(d[0]), "+f"(d[1]), "+f"(d[2]), "+f"(d[3])
        : "r"(a[0]), "r"(a[1]), "r"(a[2]), "r"(a[3]), "r"(b[0]), "r"(b[1]));
}

// ---------------------------------------------------------------------------
// nop kernels: keep the GEMM at ncu's profiled launch index (3).
// ---------------------------------------------------------------------------
__global__ void nop_kernel() {}
__global__ void nop_kernel2() {}

// ---------------------------------------------------------------------------
// Kernel A: fused bf16 hi/lo split + squared norms. One warp per row.
// ---------------------------------------------------------------------------
__device__ __forceinline__ uint32_t pack2(__nv_bfloat16 a, __nv_bfloat16 b) {
    return (uint32_t)__bfloat16_as_ushort(a) | ((uint32_t)__bfloat16_as_ushort(b) << 16);
}
__device__ __forceinline__ uint2 split8(float4 v, uint2& lo_out) {
    __nv_bfloat16 h0 = __float2bfloat16(v.x), h1 = __float2bfloat16(v.y);
    __nv_bfloat16 h2 = __float2bfloat16(v.z), h3 = __float2bfloat16(v.w);
    __nv_bfloat16 l0 = __float2bfloat16(v.x - __bfloat162float(h0));
    __nv_bfloat16 l1 = __float2bfloat16(v.y - __bfloat162float(h1));
    __nv_bfloat16 l2 = __float2bfloat16(v.z - __bfloat162float(h2));
    __nv_bfloat16 l3 = __float2bfloat16(v.w - __bfloat162float(h3));
    lo_out = make_uint2(pack2(l0, l1), pack2(l2, l3));
    return make_uint2(pack2(h0, h1), pack2(h2, h3));
}
__global__ void prep_kernel(const float* __restrict__ z, const float* __restrict__ cb) {
    int w    = (blockIdx.x * blockDim.x + threadIdx.x) >> 5;
    int lane = threadIdx.x & 31;
    if (w >= BN_ROWS + KCODES) return;
    const float* src; __nv_bfloat16 *hi_b, *lo_b;
    if (w < BN_ROWS) { src = z  + (size_t)w * DDIM;
                       hi_b = g_zhi + (size_t)w * DDIM; lo_b = g_zlo + (size_t)w * DDIM; }
    else             { int j = w - BN_ROWS; src = cb + (size_t)j * DDIM;
                       hi_b = g_chi + (size_t)j * DDIM; lo_b = g_clo + (size_t)j * DDIM; }
    const float4* p = (const float4*)src;
    float4 u = p[lane];
    float4 v = p[lane + 32];
    uint2 ulo, vlo;
    uint2 uhi = split8(u, ulo);
    uint2 vhi = split8(v, vlo);
    ((uint2*)hi_b)[lane]      = uhi;
    ((uint2*)hi_b)[lane + 32] = vhi;
    ((uint2*)lo_b)[lane]      = ulo;
    ((uint2*)lo_b)[lane + 32] = vlo;
    float s = u.x*u.x + u.y*u.y + u.z*u.z + u.w*u.w
            + v.x*v.x + v.y*v.y + v.z*v.z + v.w*v.w;
    #pragma unroll
    for (int o = 16; o > 0; o >>= 1) s += __shfl_xor_sync(0xffffffffu, s, o);
    if (lane == 0) {
        if (w < BN_ROWS) g_znorm[w] = s;
        else             g_cnorm[w - BN_ROWS] = s;
    }
}

// ---------------------------------------------------------------------------
// Kernel C: HMMA GEMM (3-term bf16 split) + dist epilogue + fused argmax.
// R13-proven champion: 3-stage cp.async pipeline, single __syncthreads per
// chunk, SW64 smem, kstep-1 A prefetch, single-pass slab epilogue (2 barriers).
// ---------------------------------------------------------------------------
__global__ void __launch_bounds__(256, 2) gemm_dist_kernel(float* __restrict__ dist) {
    extern __shared__ char smem[];
    const uint32_t sb = smem_u32(smem);
    const int t    = threadIdx.x;
    const int wid  = t >> 5;
    const int lane = t & 31;
    const int m0 = blockIdx.y * MT;
    const int n0 = blockIdx.x * NT;
    const int wm = (wid >> 1) * 32;   // warp row base within tile
    const int wn = (wid & 1) * 64;    // warp col base within tile

    // stage cn / zn
    if (t < 128)      ((float*)(smem + CN_OFF))[t]       = g_cnorm[n0 + t];
    else              ((float*)(smem + ZN_OFF))[t - 128] = g_znorm[m0 + t - 128];

    float acc[2][8][4];
    #pragma unroll
    for (int a = 0; a < 2; a++)
        #pragma unroll
        for (int b = 0; b < 8; b++)
            #pragma unroll
            for (int c = 0; c < 4; c++) acc[a][b][c] = 0.f;

    // lane decomposition for LDSM fragments
    const int arow = (lane & 7) + ((lane >> 3) & 1) * 8;   // row within 16
    const int a16  = (lane >> 4) & 1;                      // 16B col select
    const int brow = ((lane >> 4) & 1) * 8 + (lane & 7);
    const int b16  = (lane >> 3) & 1;

    auto load_stage = [&](int chunk, int stg) {
        const uint32_t dstb = sb + stg * STAGE_BYTES;
        const int k0 = chunk * KC;
        #pragma unroll
        for (int q = 0; q < 2; q++) {
            int i   = t + q * 256;        // 0..511
            int row = i >> 2, ch = i & 3;
            uint32_t d = SWZ64((uint32_t)(row * ROWB + ch * 16));
            size_t ga = (size_t)(m0 + row) * DDIM + k0 + ch * 8;
            size_t gb = (size_t)(n0 + row) * DDIM + k0 + ch * 8;
            cp16(dstb + A_HI_OFF + d, g_zhi + ga);
            cp16(dstb + A_LO_OFF + d, g_zlo + ga);
            cp16(dstb + B_HI_OFF + d, g_chi + gb);
            cp16(dstb + B_LO_OFF + d, g_clo + gb);
        }
    };

    // prologue: 2 stages in flight
    load_stage(0, 0);
    asm volatile("cp.async.commit_group;");
    load_stage(1, 1);
    asm volatile("cp.async.commit_group;");
    asm volatile("cp.async.wait_group 1;");
    __syncthreads();

    #pragma unroll 1
    for (int c = 0; c < NKCH; c++) {
        const uint32_t st = sb + (c % NSTAGE) * STAGE_BYTES;

        // ---- compute chunk c ----
        uint32_t ah[2][2][4], al[2][2][4];
        #pragma unroll
        for (int mt = 0; mt < 2; mt++) {
            uint32_t ad = SWZ64((uint32_t)((wm + mt*16 + arow) * ROWB + a16 * 16));
            ldsm_x4(ah[0][mt], st + A_HI_OFF + ad);
            ldsm_x4(al[0][mt], st + A_LO_OFF + ad);
        }
        #pragma unroll
        for (int s = 0; s < 2; s++) {
            #pragma unroll
            for (int j2 = 0; j2 < 2; j2++) {
                if (s == 0 && j2 == 1) {
                    // prefetch kstep-1 A fragments during kstep-0 MMAs
                    #pragma unroll
                    for (int mt = 0; mt < 2; mt++) {
                        uint32_t ad = SWZ64((uint32_t)((wm + mt*16 + arow) * ROWB
                                                       + 32 + a16 * 16));
                        ldsm_x4(ah[1][mt], st + A_HI_OFF + ad);
                        ldsm_x4(al[1][mt], st + A_LO_OFF + ad);
                    }
                }
                uint32_t bh[2][4], bl[2][4];
                #pragma unroll
                for (int jj = 0; jj < 2; jj++) {
                    uint32_t bd = SWZ64((uint32_t)((wn + (2*j2 + jj)*16 + brow) * ROWB
                                                   + s * 32 + b16 * 16));
                    ldsm_x4(bh[jj], st + B_HI_OFF + bd);
                    ldsm_x4(bl[jj], st + B_LO_OFF + bd);
                }
                #pragma unroll
                for (int jj = 0; jj < 2; jj++)
                    #pragma unroll
                    for (int mt = 0; mt < 2; mt++) {
                        mma_bf16(acc[mt][4*j2 + 2*jj],     ah[s][mt], bh[jj]);
                        mma_bf16(acc[mt][4*j2 + 2*jj + 1], ah[s][mt], bh[jj] + 2);
                    }
                #pragma unroll
                for (int jj = 0; jj < 2; jj++)
                    #pragma unroll
                    for (int mt = 0; mt < 2; mt++) {
                        mma_bf16(acc[mt][4*j2 + 2*jj],     ah[s][mt], bl[jj]);
                        mma_bf16(acc[mt][4*j2 + 2*jj + 1], ah[s][mt], bl[jj] + 2);
                    }
                #pragma unroll
                for (int jj = 0; jj < 2; jj++)
                    #pragma unroll
                    for (int mt = 0; mt < 2; mt++) {
                        mma_bf16(acc[mt][4*j2 + 2*jj],     al[s][mt], bh[jj]);
                        mma_bf16(acc[mt][4*j2 + 2*jj + 1], al[s][mt], bh[jj] + 2);
                    }
            }
        }

        // ---- pipeline bookkeeping: issue c+2, wait c+1, one barrier ----
        if (c + 2 < NKCH) {
            load_stage(c + 2, (c + 2) % NSTAGE);
            asm volatile("cp.async.commit_group;");
        }
        if (c < NKCH - 2) {
            asm volatile("cp.async.wait_group 1;");
            __syncthreads();
        } else if (c == NKCH - 2) {
            asm volatile("cp.async.wait_group 0;");
            __syncthreads();
        }
        // c == NKCH-1: the epilogue barrier below fences slab reuse
    }

    // ---------------- epilogue: single-pass slab + fused argmax ----------------
    const float* cns = (const float*)(smem + CN_OFF);
    const float* zns = (const float*)(smem + ZN_OFF);
    float (*slab)[132] = (float (*)[132])smem;   // 128x132x4B = 67584 <= 98304

    float best[2][2]; int bidx[2][2];
    #pragma unroll
    for (int a = 0; a < 2; a++)
        #pragma unroll
        for (int b = 0; b < 2; b++) { best[a][b] = -3.402823466e38f; bidx[a][b] = 0x7fffffff; }

    __syncthreads();   // all warps done reading stage smem before slab overwrite
    #pragma unroll
    for (int mt = 0; mt < 2; mt++)
        #pragma unroll
        for (int nt = 0; nt < 8; nt++)
            #pragma unroll
            for (int k = 0; k < 4; k++) {
                int rr   = k >> 1;
                int lrow = wm + mt * 16 + (lane >> 2) + rr * 8;
                int col  = wn + nt * 8 + (lane & 3) * 2 + (k & 1);
                float v = fmaf(2.0f, acc[mt][nt][k], -(zns[lrow] + cns[col]));
                slab[lrow][col] = v;
                if (v > best[mt][rr]) { best[mt][rr] = v; bidx[mt][rr] = n0 + col; }
            }
    __syncthreads();
    // coalesced scalar stores (dist base is odd-float offset -> no vectors)
    #pragma unroll
    for (int q = 0; q < 64; q++) {
        int lin = q * 256 + t;        // 0..16383
        int r   = lin >> 7;           // 0..127
        int col = lin & 127;
        dist[(size_t)(m0 + r) * KCODES + n0 + col] = slab[r][col];
    }

    // reduce argmax across the 4 lanes sharing each row
    #pragma unroll
    for (int mt = 0; mt < 2; mt++)
        #pragma unroll
        for (int rr = 0; rr < 2; rr++) {
            float v = best[mt][rr]; int bi = bidx[mt][rr];
            #pragma unroll
            for (int o = 1; o <= 2; o <<= 1) {
                float ov = __shfl_xor_sync(0xffffffffu, v, o);
                int   oi = __shfl_xor_sync(0xffffffffu, bi, o);
                if (ov > v || (ov == v && oi < bi)) { v = ov; bi = oi; }
            }
            if ((lane & 3) == 0) {
                int row = m0 + wm + mt * 16 + (lane >> 2) + rr * 8;
                size_t slot = (size_t)row * NHALF + blockIdx.x * 2 + (wid & 1);
                g_bestv[slot] = v;
                g_besti[slot] = bi;
            }
        }
}

// ---------------------------------------------------------------------------
// Kernel D: MERGED final argmax + zq gather + straight-through + loss partial.
// 256 threads = 4 rows x 64 threads (2 warps per row).
// Phase 1: the 2 warps of a row reduce its 128 candidate slots.
// Phase 2: the same 64 threads gather zq (float4) and form the loss partial.
// ---------------------------------------------------------------------------
__global__ void tail_kernel(const float* __restrict__ z, const float* __restrict__ cb,
                            float* __restrict__ out_zq, float* __restrict__ out_idx) {
    const int sub  = threadIdx.x >> 6;         // row within block (0..3)
    const int t64  = threadIdx.x & 63;         // thread within row
    const int w2   = t64 >> 5;                 // warp within row (0/1)
    const int lane = threadIdx.x & 31;
    const int row  = blockIdx.x * 4 + sub;

    __shared__ float sv[4][2];
    __shared__ int   si[4][2];
    __shared__ int   sidx[4];
    __shared__ float sls[4][2];

    // ---- phase 1: argmax over 128 slots (each thread: 2 slots) ----
    {
        size_t base = (size_t)row * NHALF + w2 * 64 + lane * 2;
        float v0 = g_bestv[base],     v1 = g_bestv[base + 1];
        int   i0 = g_besti[base],     i1 = g_besti[base + 1];
        float v; int bi;
        if (v1 > v0 || (v1 == v0 && i1 < i0)) { v = v1; bi = i1; }
        else                                  { v = v0; bi = i0; }
        #pragma unroll
        for (int o = 16; o > 0; o >>= 1) {
            float ov = __shfl_xor_sync(0xffffffffu, v, o);
            int   oi = __shfl_xor_sync(0xffffffffu, bi, o);
            if (ov > v || (ov == v && oi < bi)) { v = ov; bi = oi; }
        }
        if (lane == 0) { sv[sub][w2] = v; si[sub][w2] = bi; }
    }
    __syncthreads();
    if (t64 == 0) {
        float v0 = sv[sub][0], v1 = sv[sub][1];
        int   i0 = si[sub][0], i1 = si[sub][1];
        int bi = (v1 > v0 || (v1 == v0 && i1 < i0)) ? i1 : i0;
        sidx[sub] = bi;
        out_idx[row] = (float)bi;
    }
    __syncthreads();

    // ---- phase 2: zq gather + straight-through + loss partial ----
    const int idx = sidx[sub];
    const float4* zp = (const float4*)(z  + (size_t)row * DDIM);
    const float4* cp = (const float4*)(cb + (size_t)idx * DDIM);
    float4 zv = zp[t64], cv = cp[t64];
    float4 d  = make_float4(cv.x - zv.x, cv.y - zv.y, cv.z - zv.z, cv.w - zv.w);
    ((float4*)(out_zq + (size_t)row * DDIM))[t64] =
        make_float4(zv.x + d.x, zv.y + d.y, zv.z + d.z, zv.w + d.w);
    float s = d.x*d.x + d.y*d.y + d.z*d.z + d.w*d.w;
    #pragma unroll
    for (int o = 16; o > 0; o >>= 1) s += __shfl_xor_sync(0xffffffffu, s, o);
    if (lane == 0) sls[sub][w2] = s;
    __syncthreads();
    if (t64 == 0) g_partial[row] = sls[sub][0] + sls[sub][1];
}

// ---------------------------------------------------------------------------
// Kernel F: deterministic final loss reduction
// ---------------------------------------------------------------------------
__global__ void finalize_kernel(float* __restrict__ out_loss) {
    int t = threadIdx.x;
    float s = 0.0f;
    for (int i = t; i < BN_ROWS; i += 256) s += g_partial[i];
    __shared__ float sm[256];
    sm[t] = s;
    __syncthreads();
    for (int o = 128; o > 0; o >>= 1) { if (t < o) sm[t] += sm[t + o]; __syncthreads(); }
    if (t == 0) out_loss[0] = sm[0] / (float)(BN_ROWS * DDIM);
}

// ---------------------------------------------------------------------------
extern "C" void kernel_launch(void* const* d_in, const int* in_sizes, int n_in,
                              void* d_out, int out_size) {
    const float* z  = (const float*)d_in[0];
    const float* cb = (const float*)d_in[1];
    float* out      = (float*)d_out;
    float* out_zq   = out + ZQ_OFF;
    float* out_idx  = out + IDX_OFF;
    float* out_loss = out + LOSS_OFF;
    float* out_dist = out + DIST_OFF;

    cudaFuncSetAttribute(gemm_dist_kernel,
                         cudaFuncAttributeMaxDynamicSharedMemorySize, SMEM_DYN);

    prep_kernel<<<(BN_ROWS + KCODES) / 8, 256>>>(z, cb);        // launch 0 (split+norms)
    nop_kernel<<<1, 32>>>();                                     // launch 1 (slot shim)
    nop_kernel2<<<1, 32>>>();                                    // launch 2 (slot shim)
    gemm_dist_kernel<<<dim3(KCODES / NT, BN_ROWS / MT), 256, SMEM_DYN>>>(out_dist); // launch 3
    tail_kernel<<<BN_ROWS / 4, 256>>>(z, cb, out_zq, out_idx);   // argmax+zq+loss merged
    finalize_kernel<<<1, 256>>>(out_loss);
}

// round 16
// speedup vs baseline: 1.0559x; 1.0207x over previous
#include <cuda_runtime.h>
#include <cuda_bf16.h>
#include <cstdint>
#include <cstddef>

// ---------------- problem shape / output packing ----------------
#define BN_ROWS 16384
#define KCODES  8192
#define DDIM    256

#define ZQ_OFF   0
#define IDX_OFF  4194304
#define LOSS_OFF 4210688
#define DIST_OFF 4210689

// ---------------- GEMM tiling ----------------
#define MT 128              // rows per CTA tile
#define NT 128              // codes per CTA tile
#define KC 32               // K chunk (bf16 elems) = one 64B smem row
#define NKCH (DDIM/KC)      // 8 chunks
#define NHALF (KCODES/64)   // 128 argmax candidate slots per row

// smem: SW64-swizzled 64B rows (conflict-free LDSM, no padding)
#define ROWB 64
#define A_HI_OFF 0
#define A_LO_OFF 8192
#define B_HI_OFF 16384
#define B_LO_OFF 24576
#define STAGE_BYTES 32768
#define NSTAGE 3
#define CN_OFF 98304
#define ZN_OFF 98816
#define SMEM_DYN 99328

// SW64 swizzle: XOR bits[5:4] with bits[9:8] (8-row x 64B atom)
#define SWZ64(o) ((o) ^ (((o) >> 3) & 0x30))

// ---------------- device scratch (allocation-free rule) ----------------
__device__ __nv_bfloat16 g_zhi[BN_ROWS*DDIM];
__device__ __nv_bfloat16 g_zlo[BN_ROWS*DDIM];
__device__ __nv_bfloat16 g_chi[KCODES*DDIM];
__device__ __nv_bfloat16 g_clo[KCODES*DDIM];
__device__ float g_znorm[BN_ROWS];
__device__ float g_cnorm[KCODES];
__device__ float g_bestv[(size_t)BN_ROWS*NHALF];
__device__ int   g_besti[(size_t)BN_ROWS*NHALF];
__device__ float g_partial[BN_ROWS];

// ---------------- PTX helpers (all valid on plain sm_103 target) -------------
__device__ __forceinline__ uint32_t smem_u32(const void* p) {
    uint32_t a;
    asm("{ .reg .u64 t; cvta.to.shared.u64 t, %1; cvt.u32.u64 %0, t; }" : "=r"(a) : "l"(p));
    return a;
}
__device__ __forceinline__ void cp16(uint32_t saddr, const void* g) {
    asm volatile("cp.async.cg.shared.global [%0], [%1], 16;" :: "r"(saddr), "l"(g));
}
__device__ __forceinline__ void ldsm_x4(uint32_t* r, uint32_t addr) {
    asm volatile("ldmatrix.sync.aligned.m8n8.x4.shared.b16 {%0,%1,%2,%3}, [%4];"
                 : "=r"(r[0]), "=r"(r[1]), "=r"(r[2]), "=r"(r[3]) : "r"(addr));
}
__device__ __forceinline__ void mma_bf16(float* d, const uint32_t* a, const uint32_t* b) {
    asm volatile(
        "mma.sync.aligned.m16n8k16.row.col.f32.bf16.bf16.f32 "
        "{%0,%1,%2,%3}, {%4,%5,%6,%7}, {%8,%9}, {%0,%1,%2,%3};"
        : "+f"(d[0]), "+f"(d[1]), "+f"(d[2]), "+f"(d[3])
        : "r"(a[0]), "r"(a[1]), "r"(a[2]), "r"(a[3]), "r"(b[0]), "r"(b[1]));
}
__device__ __forceinline__ void stg_cs(float* p, float v) {
    asm volatile("st.global.cs.f32 [%0], %1;" :: "l"(p), "f"(v) : "memory");
}

// ---------------------------------------------------------------------------
// Kernel A: fused bf16 hi/lo split + squared norms. One warp per row.
// ---------------------------------------------------------------------------
__device__ __forceinline__ uint32_t pack2(__nv_bfloat16 a, __nv_bfloat16 b) {
    return (uint32_t)__bfloat16_as_ushort(a) | ((uint32_t)__bfloat16_as_ushort(b) << 16);
}
__device__ __forceinline__ uint2 split8(float4 v, uint2& lo_out) {
    __nv_bfloat16 h0 = __float2bfloat16(v.x), h1 = __float2bfloat16(v.y);
    __nv_bfloat16 h2 = __float2bfloat16(v.z), h3 = __float2bfloat16(v.w);
    __nv_bfloat16 l0 = __float2bfloat16(v.x - __bfloat162float(h0));
    __nv_bfloat16 l1 = __float2bfloat16(v.y - __bfloat162float(h1));
    __nv_bfloat16 l2 = __float2bfloat16(v.z - __bfloat162float(h2));
    __nv_bfloat16 l3 = __float2bfloat16(v.w - __bfloat162float(h3));
    lo_out = make_uint2(pack2(l0, l1), pack2(l2, l3));
    return make_uint2(pack2(h0, h1), pack2(h2, h3));
}
__global__ void prep_kernel(const float* __restrict__ z, const float* __restrict__ cb) {
    int w    = (blockIdx.x * blockDim.x + threadIdx.x) >> 5;
    int lane = threadIdx.x & 31;
    if (w >= BN_ROWS + KCODES) return;
    const float* src; __nv_bfloat16 *hi_b, *lo_b;
    if (w < BN_ROWS) { src = z  + (size_t)w * DDIM;
                       hi_b = g_zhi + (size_t)w * DDIM; lo_b = g_zlo + (size_t)w * DDIM; }
    else             { int j = w - BN_ROWS; src = cb + (size_t)j * DDIM;
                       hi_b = g_chi + (size_t)j * DDIM; lo_b = g_clo + (size_t)j * DDIM; }
    const float4* p = (const float4*)src;
    float4 u = p[lane];
    float4 v = p[lane + 32];
    uint2 ulo, vlo;
    uint2 uhi = split8(u, ulo);
    uint2 vhi = split8(v, vlo);
    ((uint2*)hi_b)[lane]      = uhi;
    ((uint2*)hi_b)[lane + 32] = vhi;
    ((uint2*)lo_b)[lane]      = ulo;
    ((uint2*)lo_b)[lane + 32] = vlo;
    float s = u.x*u.x + u.y*u.y + u.z*u.z + u.w*u.w
            + v.x*v.x + v.y*v.y + v.z*v.z + v.w*v.w;
    #pragma unroll
    for (int o = 16; o > 0; o >>= 1) s += __shfl_xor_sync(0xffffffffu, s, o);
    if (lane == 0) {
        if (w < BN_ROWS) g_znorm[w] = s;
        else             g_cnorm[w - BN_ROWS] = s;
    }
}

// ---------------------------------------------------------------------------
// Kernel C: HMMA GEMM (3-term bf16 split) + dist epilogue + fused argmax.
// R13/R15-proven champion: 3-stage cp.async pipeline, single __syncthreads per
// chunk, SW64 smem, kstep-1 A prefetch, single-pass slab epilogue (2 barriers).
// dist stores use st.global.cs (write-once stream, keeps A/B hot in L2).
// ---------------------------------------------------------------------------
__global__ void __launch_bounds__(256, 2) gemm_dist_kernel(float* __restrict__ dist) {
    extern __shared__ char smem[];
    const uint32_t sb = smem_u32(smem);
    const int t    = threadIdx.x;
    const int wid  = t >> 5;
    const int lane = t & 31;
    const int m0 = blockIdx.y * MT;
    const int n0 = blockIdx.x * NT;
    const int wm = (wid >> 1) * 32;   // warp row base within tile
    const int wn = (wid & 1) * 64;    // warp col base within tile

    // stage cn / zn
    if (t < 128)      ((float*)(smem + CN_OFF))[t]       = g_cnorm[n0 + t];
    else              ((float*)(smem + ZN_OFF))[t - 128] = g_znorm[m0 + t - 128];

    float acc[2][8][4];
    #pragma unroll
    for (int a = 0; a < 2; a++)
        #pragma unroll
        for (int b = 0; b < 8; b++)
            #pragma unroll
            for (int c = 0; c < 4; c++) acc[a][b][c] = 0.f;

    // lane decomposition for LDSM fragments
    const int arow = (lane & 7) + ((lane >> 3) & 1) * 8;   // row within 16
    const int a16  = (lane >> 4) & 1;                      // 16B col select
    const int brow = ((lane >> 4) & 1) * 8 + (lane & 7);
    const int b16  = (lane >> 3) & 1;

    auto load_stage = [&](int chunk, int stg) {
        const uint32_t dstb = sb + stg * STAGE_BYTES;
        const int k0 = chunk * KC;
        #pragma unroll
        for (int q = 0; q < 2; q++) {
            int i   = t + q * 256;        // 0..511
            int row = i >> 2, ch = i & 3;
            uint32_t d = SWZ64((uint32_t)(row * ROWB + ch * 16));
            size_t ga = (size_t)(m0 + row) * DDIM + k0 + ch * 8;
            size_t gb = (size_t)(n0 + row) * DDIM + k0 + ch * 8;
            cp16(dstb + A_HI_OFF + d, g_zhi + ga);
            cp16(dstb + A_LO_OFF + d, g_zlo + ga);
            cp16(dstb + B_HI_OFF + d, g_chi + gb);
            cp16(dstb + B_LO_OFF + d, g_clo + gb);
        }
    };

    // prologue: 2 stages in flight
    load_stage(0, 0);
    asm volatile("cp.async.commit_group;");
    load_stage(1, 1);
    asm volatile("cp.async.commit_group;");
    asm volatile("cp.async.wait_group 1;");
    __syncthreads();

    #pragma unroll 1
    for (int c = 0; c < NKCH; c++) {
        const uint32_t st = sb + (c % NSTAGE) * STAGE_BYTES;

        // ---- compute chunk c ----
        uint32_t ah[2][2][4], al[2][2][4];
        #pragma unroll
        for (int mt = 0; mt < 2; mt++) {
            uint32_t ad = SWZ64((uint32_t)((wm + mt*16 + arow) * ROWB + a16 * 16));
            ldsm_x4(ah[0][mt], st + A_HI_OFF + ad);
            ldsm_x4(al[0][mt], st + A_LO_OFF + ad);
        }
        #pragma unroll
        for (int s = 0; s < 2; s++) {
            #pragma unroll
            for (int j2 = 0; j2 < 2; j2++) {
                if (s == 0 && j2 == 1) {
                    // prefetch kstep-1 A fragments during kstep-0 MMAs
                    #pragma unroll
                    for (int mt = 0; mt < 2; mt++) {
                        uint32_t ad = SWZ64((uint32_t)((wm + mt*16 + arow) * ROWB
                                                       + 32 + a16 * 16));
                        ldsm_x4(ah[1][mt], st + A_HI_OFF + ad);
                        ldsm_x4(al[1][mt], st + A_LO_OFF + ad);
                    }
                }
                uint32_t bh[2][4], bl[2][4];
                #pragma unroll
                for (int jj = 0; jj < 2; jj++) {
                    uint32_t bd = SWZ64((uint32_t)((wn + (2*j2 + jj)*16 + brow) * ROWB
                                                   + s * 32 + b16 * 16));
                    ldsm_x4(bh[jj], st + B_HI_OFF + bd);
                    ldsm_x4(bl[jj], st + B_LO_OFF + bd);
                }
                #pragma unroll
                for (int jj = 0; jj < 2; jj++)
                    #pragma unroll
                    for (int mt = 0; mt < 2; mt++) {
                        mma_bf16(acc[mt][4*j2 + 2*jj],     ah[s][mt], bh[jj]);
                        mma_bf16(acc[mt][4*j2 + 2*jj + 1], ah[s][mt], bh[jj] + 2);
                    }
                #pragma unroll
                for (int jj = 0; jj < 2; jj++)
                    #pragma unroll
                    for (int mt = 0; mt < 2; mt++) {
                        mma_bf16(acc[mt][4*j2 + 2*jj],     ah[s][mt], bl[jj]);
                        mma_bf16(acc[mt][4*j2 + 2*jj + 1], ah[s][mt], bl[jj] + 2);
                    }
                #pragma unroll
                for (int jj = 0; jj < 2; jj++)
                    #pragma unroll
                    for (int mt = 0; mt < 2; mt++) {
                        mma_bf16(acc[mt][4*j2 + 2*jj],     al[s][mt], bh[jj]);
                        mma_bf16(acc[mt][4*j2 + 2*jj + 1], al[s][mt], bh[jj] + 2);
                    }
            }
        }

        // ---- pipeline bookkeeping: issue c+2, wait c+1, one barrier ----
        if (c + 2 < NKCH) {
            load_stage(c + 2, (c + 2) % NSTAGE);
            asm volatile("cp.async.commit_group;");
        }
        if (c < NKCH - 2) {
            asm volatile("cp.async.wait_group 1;");
            __syncthreads();
        } else if (c == NKCH - 2) {
            asm volatile("cp.async.wait_group 0;");
            __syncthreads();
        }
        // c == NKCH-1: the epilogue barrier below fences slab reuse
    }

    // ---------------- epilogue: single-pass slab + fused argmax ----------------
    const float* cns = (const float*)(smem + CN_OFF);
    const float* zns = (const float*)(smem + ZN_OFF);
    float (*slab)[132] = (float (*)[132])smem;   // 128x132x4B = 67584 <= 98304

    float best[2][2]; int bidx[2][2];
    #pragma unroll
    for (int a = 0; a < 2; a++)
        #pragma unroll
        for (int b = 0; b < 2; b++) { best[a][b] = -3.402823466e38f; bidx[a][b] = 0x7fffffff; }

    __syncthreads();   // all warps done reading stage smem before slab overwrite
    #pragma unroll
    for (int mt = 0; mt < 2; mt++)
        #pragma unroll
        for (int nt = 0; nt < 8; nt++)
            #pragma unroll
            for (int k = 0; k < 4; k++) {
                int rr   = k >> 1;
                int lrow = wm + mt * 16 + (lane >> 2) + rr * 8;
                int col  = wn + nt * 8 + (lane & 3) * 2 + (k & 1);
                float v = fmaf(2.0f, acc[mt][nt][k], -(zns[lrow] + cns[col]));
                slab[lrow][col] = v;
                if (v > best[mt][rr]) { best[mt][rr] = v; bidx[mt][rr] = n0 + col; }
            }
    __syncthreads();
    // coalesced scalar streaming stores (dist base is odd-float offset)
    #pragma unroll
    for (int q = 0; q < 64; q++) {
        int lin = q * 256 + t;        // 0..16383
        int r   = lin >> 7;           // 0..127
        int col = lin & 127;
        stg_cs(dist + (size_t)(m0 + r) * KCODES + n0 + col, slab[r][col]);
    }

    // reduce argmax across the 4 lanes sharing each row
    #pragma unroll
    for (int mt = 0; mt < 2; mt++)
        #pragma unroll
        for (int rr = 0; rr < 2; rr++) {
            float v = best[mt][rr]; int bi = bidx[mt][rr];
            #pragma unroll
            for (int o = 1; o <= 2; o <<= 1) {
                float ov = __shfl_xor_sync(0xffffffffu, v, o);
                int   oi = __shfl_xor_sync(0xffffffffu, bi, o);
                if (ov > v || (ov == v && oi < bi)) { v = ov; bi = oi; }
            }
            if ((lane & 3) == 0) {
                int row = m0 + wm + mt * 16 + (lane >> 2) + rr * 8;
                size_t slot = (size_t)row * NHALF + blockIdx.x * 2 + (wid & 1);
                g_bestv[slot] = v;
                g_besti[slot] = bi;
            }
        }
}

// ---------------------------------------------------------------------------
// Kernel D: MERGED final argmax + zq gather + straight-through + loss partial.
// 256 threads = 4 rows x 64 threads (2 warps per row).
// ---------------------------------------------------------------------------
__global__ void tail_kernel(const float* __restrict__ z, const float* __restrict__ cb,
                            float* __restrict__ out_zq, float* __restrict__ out_idx) {
    const int sub  = threadIdx.x >> 6;         // row within block (0..3)
    const int t64  = threadIdx.x & 63;         // thread within row
    const int w2   = t64 >> 5;                 // warp within row (0/1)
    const int lane = threadIdx.x & 31;
    const int row  = blockIdx.x * 4 + sub;

    __shared__ float sv[4][2];
    __shared__ int   si[4][2];
    __shared__ int   sidx[4];
    __shared__ float sls[4][2];

    // ---- phase 1: argmax over 128 slots (each thread: 2 slots) ----
    {
        size_t base = (size_t)row * NHALF + w2 * 64 + lane * 2;
        float v0 = g_bestv[base],     v1 = g_bestv[base + 1];
        int   i0 = g_besti[base],     i1 = g_besti[base + 1];
        float v; int bi;
        if (v1 > v0 || (v1 == v0 && i1 < i0)) { v = v1; bi = i1; }
        else                                  { v = v0; bi = i0; }
        #pragma unroll
        for (int o = 16; o > 0; o >>= 1) {
            float ov = __shfl_xor_sync(0xffffffffu, v, o);
            int   oi = __shfl_xor_sync(0xffffffffu, bi, o);
            if (ov > v || (ov == v && oi < bi)) { v = ov; bi = oi; }
        }
        if (lane == 0) { sv[sub][w2] = v; si[sub][w2] = bi; }
    }
    __syncthreads();
    if (t64 == 0) {
        float v0 = sv[sub][0], v1 = sv[sub][1];
        int   i0 = si[sub][0], i1 = si[sub][1];
        int bi = (v1 > v0 || (v1 == v0 && i1 < i0)) ? i1 : i0;
        sidx[sub] = bi;
        out_idx[row] = (float)bi;
    }
    __syncthreads();

    // ---- phase 2: zq gather + straight-through + loss partial ----
    const int idx = sidx[sub];
    const float4* zp = (const float4*)(z  + (size_t)row * DDIM);
    const float4* cp = (const float4*)(cb + (size_t)idx * DDIM);
    float4 zv = zp[t64], cv = cp[t64];
    float4 d  = make_float4(cv.x - zv.x, cv.y - zv.y, cv.z - zv.z, cv.w - zv.w);
    ((float4*)(out_zq + (size_t)row * DDIM))[t64] =
        make_float4(zv.x + d.x, zv.y + d.y, zv.z + d.z, zv.w + d.w);
    float s = d.x*d.x + d.y*d.y + d.z*d.z + d.w*d.w;
    #pragma unroll
    for (int o = 16; o > 0; o >>= 1) s += __shfl_xor_sync(0xffffffffu, s, o);
    if (lane == 0) sls[sub][w2] = s;
    __syncthreads();
    if (t64 == 0) g_partial[row] = sls[sub][0] + sls[sub][1];
}

// ---------------------------------------------------------------------------
// Kernel F: deterministic final loss reduction
// ---------------------------------------------------------------------------
__global__ void finalize_kernel(float* __restrict__ out_loss) {
    int t = threadIdx.x;
    float s = 0.0f;
    for (int i = t; i < BN_ROWS; i += 256) s += g_partial[i];
    __shared__ float sm[256];
    sm[t] = s;
    __syncthreads();
    for (int o = 128; o > 0; o >>= 1) { if (t < o) sm[t] += sm[t + o]; __syncthreads(); }
    if (t == 0) out_loss[0] = sm[0] / (float)(BN_ROWS * DDIM);
}

// ---------------------------------------------------------------------------
extern "C" void kernel_launch(void* const* d_in, const int* in_sizes, int n_in,
                              void* d_out, int out_size) {
    const float* z  = (const float*)d_in[0];
    const float* cb = (const float*)d_in[1];
    float* out      = (float*)d_out;
    float* out_zq   = out + ZQ_OFF;
    float* out_idx  = out + IDX_OFF;
    float* out_loss = out + LOSS_OFF;
    float* out_dist = out + DIST_OFF;

    cudaFuncSetAttribute(gemm_dist_kernel,
                         cudaFuncAttributeMaxDynamicSharedMemorySize, SMEM_DYN);

    prep_kernel<<<(BN_ROWS + KCODES) / 8, 256>>>(z, cb);
    gemm_dist_kernel<<<dim3(KCODES / NT, BN_ROWS / MT), 256, SMEM_DYN>>>(out_dist);
    tail_kernel<<<BN_ROWS / 4, 256>>>(z, cb, out_zq, out_idx);
    finalize_kernel<<<1, 256>>>(out_loss);
}

// round 17
// speedup vs baseline: 1.0590x; 1.0029x over previous
#include <cuda_runtime.h>
#include <cuda_bf16.h>
#include <cstdint>
#include <cstddef>

// ---------------- problem shape / output packing ----------------
#define BN_ROWS 16384
#define KCODES  8192
#define DDIM    256

#define ZQ_OFF   0
#define IDX_OFF  4194304
#define LOSS_OFF 4210688
#define DIST_OFF 4210689

// ---------------- GEMM tiling ----------------
#define MT 128              // rows per CTA tile
#define NT 128              // codes per CTA tile
#define KC 32               // K chunk (bf16 elems) = one 64B smem row
#define NKCH (DDIM/KC)      // 8 chunks
#define NHALF (KCODES/64)   // 128 argmax candidate slots per row

// smem: SW64-swizzled 64B rows (conflict-free LDSM, no padding)
#define ROWB 64
#define A_HI_OFF 0
#define A_LO_OFF 8192
#define B_HI_OFF 16384
#define B_LO_OFF 24576
#define STAGE_BYTES 32768
#define NSTAGE 3
#define CN_OFF 98304
#define ZN_OFF 98816
#define SMEM_DYN 99328

// SW64 swizzle: XOR bits[5:4] with bits[9:8] (8-row x 64B atom)
#define SWZ64(o) ((o) ^ (((o) >> 3) & 0x30))

// ---------------- device scratch (allocation-free rule) ----------------
__device__ __nv_bfloat16 g_zhi[BN_ROWS*DDIM];
__device__ __nv_bfloat16 g_zlo[BN_ROWS*DDIM];
__device__ __nv_bfloat16 g_chi[KCODES*DDIM];
__device__ __nv_bfloat16 g_clo[KCODES*DDIM];
__device__ float g_znorm[BN_ROWS];
__device__ float g_cnorm[KCODES];
__device__ float g_bestv[(size_t)BN_ROWS*NHALF];
__device__ int   g_besti[(size_t)BN_ROWS*NHALF];
__device__ float g_partial[BN_ROWS];

// ---------------- PTX helpers (all valid on plain sm_103 target) -------------
__device__ __forceinline__ uint32_t smem_u32(const void* p) {
    uint32_t a;
    asm("{ .reg .u64 t; cvta.to.shared.u64 t, %1; cvt.u32.u64 %0, t; }" : "=r"(a) : "l"(p));
    return a;
}
__device__ __forceinline__ void cp16(uint32_t saddr, const void* g) {
    asm volatile("cp.async.cg.shared.global [%0], [%1], 16;" :: "r"(saddr), "l"(g));
}
__device__ __forceinline__ void ldsm_x4(uint32_t* r, uint32_t addr) {
    asm volatile("ldmatrix.sync.aligned.m8n8.x4.shared.b16 {%0,%1,%2,%3}, [%4];"
                 : "=r"(r[0]), "=r"(r[1]), "=r"(r[2]), "=r"(r[3]) : "r"(addr));
}
__device__ __forceinline__ void mma_bf16(float* d, const uint32_t* a, const uint32_t* b) {
    asm volatile(
        "mma.sync.aligned.m16n8k16.row.col.f32.bf16.bf16.f32 "
        "{%0,%1,%2,%3}, {%4,%5,%6,%7}, {%8,%9}, {%0,%1,%2,%3};"
        : "+f"(d[0]), "+f"(d[1]), "+f"(d[2]), "+f"(d[3])
        : "r"(a[0]), "r"(a[1]), "r"(a[2]), "r"(a[3]), "r"(b[0]), "r"(b[1]));
}
__device__ __forceinline__ void stg_cs(float* p, float v) {
    asm volatile("st.global.cs.f32 [%0], %1;" :: "l"(p), "f"(v) : "memory");
}

// ---------------------------------------------------------------------------
// Kernel A: fused bf16 hi/lo split + squared norms. One warp per row.
// ---------------------------------------------------------------------------
__device__ __forceinline__ uint32_t pack2(__nv_bfloat16 a, __nv_bfloat16 b) {
    return (uint32_t)__bfloat16_as_ushort(a) | ((uint32_t)__bfloat16_as_ushort(b) << 16);
}
__device__ __forceinline__ uint2 split8(float4 v, uint2& lo_out) {
    __nv_bfloat16 h0 = __float2bfloat16(v.x), h1 = __float2bfloat16(v.y);
    __nv_bfloat16 h2 = __float2bfloat16(v.z), h3 = __float2bfloat16(v.w);
    __nv_bfloat16 l0 = __float2bfloat16(v.x - __bfloat162float(h0));
    __nv_bfloat16 l1 = __float2bfloat16(v.y - __bfloat162float(h1));
    __nv_bfloat16 l2 = __float2bfloat16(v.z - __bfloat162float(h2));
    __nv_bfloat16 l3 = __float2bfloat16(v.w - __bfloat162float(h3));
    lo_out = make_uint2(pack2(l0, l1), pack2(l2, l3));
    return make_uint2(pack2(h0, h1), pack2(h2, h3));
}
__global__ void prep_kernel(const float* __restrict__ z, const float* __restrict__ cb) {
    int w    = (blockIdx.x * blockDim.x + threadIdx.x) >> 5;
    int lane = threadIdx.x & 31;
    if (w >= BN_ROWS + KCODES) return;
    const float* src; __nv_bfloat16 *hi_b, *lo_b;
    if (w < BN_ROWS) { src = z  + (size_t)w * DDIM;
                       hi_b = g_zhi + (size_t)w * DDIM; lo_b = g_zlo + (size_t)w * DDIM; }
    else             { int j = w - BN_ROWS; src = cb + (size_t)j * DDIM;
                       hi_b = g_chi + (size_t)j * DDIM; lo_b = g_clo + (size_t)j * DDIM; }
    const float4* p = (const float4*)src;
    float4 u = p[lane];
    float4 v = p[lane + 32];
    uint2 ulo, vlo;
    uint2 uhi = split8(u, ulo);
    uint2 vhi = split8(v, vlo);
    ((uint2*)hi_b)[lane]      = uhi;
    ((uint2*)hi_b)[lane + 32] = vhi;
    ((uint2*)lo_b)[lane]      = ulo;
    ((uint2*)lo_b)[lane + 32] = vlo;
    float s = u.x*u.x + u.y*u.y + u.z*u.z + u.w*u.w
            + v.x*v.x + v.y*v.y + v.z*v.z + v.w*v.w;
    #pragma unroll
    for (int o = 16; o > 0; o >>= 1) s += __shfl_xor_sync(0xffffffffu, s, o);
    if (lane == 0) {
        if (w < BN_ROWS) g_znorm[w] = s;
        else             g_cnorm[w - BN_ROWS] = s;
    }
}

// ---------------------------------------------------------------------------
// Kernel C: HMMA GEMM (3-term bf16 split) + dist epilogue + fused argmax.
// Champion config: 3-stage cp.async pipeline, single __syncthreads per chunk,
// SW64 smem, kstep-1 A prefetch, single-pass slab epilogue, st.cs dist stores.
// ---------------------------------------------------------------------------
__global__ void __launch_bounds__(256, 2) gemm_dist_kernel(float* __restrict__ dist) {
    extern __shared__ char smem[];
    const uint32_t sb = smem_u32(smem);
    const int t    = threadIdx.x;
    const int wid  = t >> 5;
    const int lane = t & 31;
    const int m0 = blockIdx.y * MT;
    const int n0 = blockIdx.x * NT;
    const int wm = (wid >> 1) * 32;   // warp row base within tile
    const int wn = (wid & 1) * 64;    // warp col base within tile

    // stage cn / zn
    if (t < 128)      ((float*)(smem + CN_OFF))[t]       = g_cnorm[n0 + t];
    else              ((float*)(smem + ZN_OFF))[t - 128] = g_znorm[m0 + t - 128];

    float acc[2][8][4];
    #pragma unroll
    for (int a = 0; a < 2; a++)
        #pragma unroll
        for (int b = 0; b < 8; b++)
            #pragma unroll
            for (int c = 0; c < 4; c++) acc[a][b][c] = 0.f;

    // lane decomposition for LDSM fragments
    const int arow = (lane & 7) + ((lane >> 3) & 1) * 8;   // row within 16
    const int a16  = (lane >> 4) & 1;                      // 16B col select
    const int brow = ((lane >> 4) & 1) * 8 + (lane & 7);
    const int b16  = (lane >> 3) & 1;

    auto load_stage = [&](int chunk, int stg) {
        const uint32_t dstb = sb + stg * STAGE_BYTES;
        const int k0 = chunk * KC;
        #pragma unroll
        for (int q = 0; q < 2; q++) {
            int i   = t + q * 256;        // 0..511
            int row = i >> 2, ch = i & 3;
            uint32_t d = SWZ64((uint32_t)(row * ROWB + ch * 16));
            size_t ga = (size_t)(m0 + row) * DDIM + k0 + ch * 8;
            size_t gb = (size_t)(n0 + row) * DDIM + k0 + ch * 8;
            cp16(dstb + A_HI_OFF + d, g_zhi + ga);
            cp16(dstb + A_LO_OFF + d, g_zlo + ga);
            cp16(dstb + B_HI_OFF + d, g_chi + gb);
            cp16(dstb + B_LO_OFF + d, g_clo + gb);
        }
    };

    // prologue: 2 stages in flight
    load_stage(0, 0);
    asm volatile("cp.async.commit_group;");
    load_stage(1, 1);
    asm volatile("cp.async.commit_group;");
    asm volatile("cp.async.wait_group 1;");
    __syncthreads();

    #pragma unroll 1
    for (int c = 0; c < NKCH; c++) {
        const uint32_t st = sb + (c % NSTAGE) * STAGE_BYTES;

        // ---- compute chunk c ----
        uint32_t ah[2][2][4], al[2][2][4];
        #pragma unroll
        for (int mt = 0; mt < 2; mt++) {
            uint32_t ad = SWZ64((uint32_t)((wm + mt*16 + arow) * ROWB + a16 * 16));
            ldsm_x4(ah[0][mt], st + A_HI_OFF + ad);
            ldsm_x4(al[0][mt], st + A_LO_OFF + ad);
        }
        #pragma unroll
        for (int s = 0; s < 2; s++) {
            #pragma unroll
            for (int j2 = 0; j2 < 2; j2++) {
                if (s == 0 && j2 == 1) {
                    // prefetch kstep-1 A fragments during kstep-0 MMAs
                    #pragma unroll
                    for (int mt = 0; mt < 2; mt++) {
                        uint32_t ad = SWZ64((uint32_t)((wm + mt*16 + arow) * ROWB
                                                       + 32 + a16 * 16));
                        ldsm_x4(ah[1][mt], st + A_HI_OFF + ad);
                        ldsm_x4(al[1][mt], st + A_LO_OFF + ad);
                    }
                }
                uint32_t bh[2][4], bl[2][4];
                #pragma unroll
                for (int jj = 0; jj < 2; jj++) {
                    uint32_t bd = SWZ64((uint32_t)((wn + (2*j2 + jj)*16 + brow) * ROWB
                                                   + s * 32 + b16 * 16));
                    ldsm_x4(bh[jj], st + B_HI_OFF + bd);
                    ldsm_x4(bl[jj], st + B_LO_OFF + bd);
                }
                #pragma unroll
                for (int jj = 0; jj < 2; jj++)
                    #pragma unroll
                    for (int mt = 0; mt < 2; mt++) {
                        mma_bf16(acc[mt][4*j2 + 2*jj],     ah[s][mt], bh[jj]);
                        mma_bf16(acc[mt][4*j2 + 2*jj + 1], ah[s][mt], bh[jj] + 2);
                    }
                #pragma unroll
                for (int jj = 0; jj < 2; jj++)
                    #pragma unroll
                    for (int mt = 0; mt < 2; mt++) {
                        mma_bf16(acc[mt][4*j2 + 2*jj],     ah[s][mt], bl[jj]);
                        mma_bf16(acc[mt][4*j2 + 2*jj + 1], ah[s][mt], bl[jj] + 2);
                    }
                #pragma unroll
                for (int jj = 0; jj < 2; jj++)
                    #pragma unroll
                    for (int mt = 0; mt < 2; mt++) {
                        mma_bf16(acc[mt][4*j2 + 2*jj],     al[s][mt], bh[jj]);
                        mma_bf16(acc[mt][4*j2 + 2*jj + 1], al[s][mt], bh[jj] + 2);
                    }
            }
        }

        // ---- pipeline bookkeeping: issue c+2, wait c+1, one barrier ----
        if (c + 2 < NKCH) {
            load_stage(c + 2, (c + 2) % NSTAGE);
            asm volatile("cp.async.commit_group;");
        }
        if (c < NKCH - 2) {
            asm volatile("cp.async.wait_group 1;");
            __syncthreads();
        } else if (c == NKCH - 2) {
            asm volatile("cp.async.wait_group 0;");
            __syncthreads();
        }
        // c == NKCH-1: the epilogue barrier below fences slab reuse
    }

    // ---------------- epilogue: single-pass slab + fused argmax ----------------
    const float* cns = (const float*)(smem + CN_OFF);
    const float* zns = (const float*)(smem + ZN_OFF);
    float (*slab)[132] = (float (*)[132])smem;   // 128x132x4B = 67584 <= 98304

    float best[2][2]; int bidx[2][2];
    #pragma unroll
    for (int a = 0; a < 2; a++)
        #pragma unroll
        for (int b = 0; b < 2; b++) { best[a][b] = -3.402823466e38f; bidx[a][b] = 0x7fffffff; }

    __syncthreads();   // all warps done reading stage smem before slab overwrite
    #pragma unroll
    for (int mt = 0; mt < 2; mt++)
        #pragma unroll
        for (int nt = 0; nt < 8; nt++)
            #pragma unroll
            for (int k = 0; k < 4; k++) {
                int rr   = k >> 1;
                int lrow = wm + mt * 16 + (lane >> 2) + rr * 8;
                int col  = wn + nt * 8 + (lane & 3) * 2 + (k & 1);
                float v = fmaf(2.0f, acc[mt][nt][k], -(zns[lrow] + cns[col]));
                slab[lrow][col] = v;
                if (v > best[mt][rr]) { best[mt][rr] = v; bidx[mt][rr] = n0 + col; }
            }
    __syncthreads();
    // coalesced scalar streaming stores (dist base is odd-float offset)
    #pragma unroll
    for (int q = 0; q < 64; q++) {
        int lin = q * 256 + t;        // 0..16383
        int r   = lin >> 7;           // 0..127
        int col = lin & 127;
        stg_cs(dist + (size_t)(m0 + r) * KCODES + n0 + col, slab[r][col]);
    }

    // reduce argmax across the 4 lanes sharing each row
    #pragma unroll
    for (int mt = 0; mt < 2; mt++)
        #pragma unroll
        for (int rr = 0; rr < 2; rr++) {
            float v = best[mt][rr]; int bi = bidx[mt][rr];
            #pragma unroll
            for (int o = 1; o <= 2; o <<= 1) {
                float ov = __shfl_xor_sync(0xffffffffu, v, o);
                int   oi = __shfl_xor_sync(0xffffffffu, bi, o);
                if (ov > v || (ov == v && oi < bi)) { v = ov; bi = oi; }
            }
            if ((lane & 3) == 0) {
                int row = m0 + wm + mt * 16 + (lane >> 2) + rr * 8;
                size_t slot = (size_t)row * NHALF + blockIdx.x * 2 + (wid & 1);
                g_bestv[slot] = v;
                g_besti[slot] = bi;
            }
        }
}

// ---------------------------------------------------------------------------
// Kernel D: MERGED final argmax + zq gather + straight-through + loss partial.
// 256 threads = 4 rows x 64 threads (2 warps per row).
// ---------------------------------------------------------------------------
__global__ void tail_kernel(const float* __restrict__ z, const float* __restrict__ cb,
                            float* __restrict__ out_zq, float* __restrict__ out_idx) {
    const int sub  = threadIdx.x >> 6;         // row within block (0..3)
    const int t64  = threadIdx.x & 63;         // thread within row
    const int w2   = t64 >> 5;                 // warp within row (0/1)
    const int lane = threadIdx.x & 31;
    const int row  = blockIdx.x * 4 + sub;

    __shared__ float sv[4][2];
    __shared__ int   si[4][2];
    __shared__ int   sidx[4];
    __shared__ float sls[4][2];

    // ---- phase 1: argmax over 128 slots (each thread: 2 slots) ----
    {
        size_t base = (size_t)row * NHALF + w2 * 64 + lane * 2;
        float v0 = __ldg(&g_bestv[base]),     v1 = __ldg(&g_bestv[base + 1]);
        int   i0 = __ldg(&g_besti[base]),     i1 = __ldg(&g_besti[base + 1]);
        float v; int bi;
        if (v1 > v0 || (v1 == v0 && i1 < i0)) { v = v1; bi = i1; }
        else                                  { v = v0; bi = i0; }
        #pragma unroll
        for (int o = 16; o > 0; o >>= 1) {
            float ov = __shfl_xor_sync(0xffffffffu, v, o);
            int   oi = __shfl_xor_sync(0xffffffffu, bi, o);
            if (ov > v || (ov == v && oi < bi)) { v = ov; bi = oi; }
        }
        if (lane == 0) { sv[sub][w2] = v; si[sub][w2] = bi; }
    }
    __syncthreads();
    if (t64 == 0) {
        float v0 = sv[sub][0], v1 = sv[sub][1];
        int   i0 = si[sub][0], i1 = si[sub][1];
        int bi = (v1 > v0 || (v1 == v0 && i1 < i0)) ? i1 : i0;
        sidx[sub] = bi;
        out_idx[row] = (float)bi;
    }
    __syncthreads();

    // ---- phase 2: zq gather + straight-through + loss partial ----
    const int idx = sidx[sub];
    const float4* zp = (const float4*)(z  + (size_t)row * DDIM);
    const float4* cp = (const float4*)(cb + (size_t)idx * DDIM);
    float4 zv = zp[t64], cv = cp[t64];
    float4 d  = make_float4(cv.x - zv.x, cv.y - zv.y, cv.z - zv.z, cv.w - zv.w);
    ((float4*)(out_zq + (size_t)row * DDIM))[t64] =
        make_float4(zv.x + d.x, zv.y + d.y, zv.z + d.z, zv.w + d.w);
    float s = d.x*d.x + d.y*d.y + d.z*d.z + d.w*d.w;
    #pragma unroll
    for (int o = 16; o > 0; o >>= 1) s += __shfl_xor_sync(0xffffffffu, s, o);
    if (lane == 0) sls[sub][w2] = s;
    __syncthreads();
    if (t64 == 0) g_partial[row] = sls[sub][0] + sls[sub][1];
}

// ---------------------------------------------------------------------------
// Kernel F: final loss reduction. 1024 threads, float4 loads (MLP=4/thread).
// Deterministic fixed-order tree (no atomics).
// ---------------------------------------------------------------------------
__global__ void finalize_kernel(float* __restrict__ out_loss) {
    int t = threadIdx.x;
    const float4* p = (const float4*)g_partial;   // 4096 float4
    float s = 0.0f;
    #pragma unroll
    for (int q = 0; q < 4; q++) {
        float4 v = p[t + q * 1024];
        s += v.x + v.y + v.z + v.w;
    }
    __shared__ float sm[1024];
    sm[t] = s;
    __syncthreads();
    for (int o = 512; o > 0; o >>= 1) { if (t < o) sm[t] += sm[t + o]; __syncthreads(); }
    if (t == 0) out_loss[0] = sm[0] / (float)(BN_ROWS * DDIM);
}

// ---------------------------------------------------------------------------
extern "C" void kernel_launch(void* const* d_in, const int* in_sizes, int n_in,
                              void* d_out, int out_size) {
    const float* z  = (const float*)d_in[0];
    const float* cb = (const float*)d_in[1];
    float* out      = (float*)d_out;
    float* out_zq   = out + ZQ_OFF;
    float* out_idx  = out + IDX_OFF;
    float* out_loss = out + LOSS_OFF;
    float* out_dist = out + DIST_OFF;

    cudaFuncSetAttribute(gemm_dist_kernel,
                         cudaFuncAttributeMaxDynamicSharedMemorySize, SMEM_DYN);

    prep_kernel<<<(BN_ROWS + KCODES) / 8, 256>>>(z, cb);
    gemm_dist_kernel<<<dim3(KCODES / NT, BN_ROWS / MT), 256, SMEM_DYN>>>(out_dist);
    tail_kernel<<<BN_ROWS / 4, 256>>>(z, cb, out_zq, out_idx);
    finalize_kernel<<<1, 1024>>>(out_loss);
}